// round 5
// baseline (speedup 1.0000x reference)
#include <cuda_runtime.h>
#include <cuda_bf16.h>

// PointInstanceNorm, fused persistent version.
// x: [N,D] fp32; seqlen: [B+1] cumulative; weight/bias: [D].
// out[i,d] = (x[i,d]-mean[b,d]) * rsqrt(var[b,d]+eps) * w[d] + bias[d].
//
// Key idea: one segment (32 MB at B=16,N=1e6,D=128) fits in L2 (126 MB).
// A persistent kernel processes segments in order:
//     reduce(b) -> grid barrier -> local finalize -> normalize(b)
// so the second read of segment b hits L2, cutting DRAM traffic 1.5GB -> ~1.0GB.
// out writes use .cs (evict-first) to avoid evicting the hot x tiles.

#define PIN_EPS 1e-5f
#define PIN_MAXBD (1 << 20)

__device__ float g_sum[PIN_MAXBD];
__device__ float g_sq [PIN_MAXBD];
// extra scratch for the fallback path
__device__ float g_scale[PIN_MAXBD];
__device__ float g_shift[PIN_MAXBD];

// ---- software grid barrier (generation counter; wrap-safe across replays) ----
__device__ unsigned g_bar_gen   = 0;
__device__ unsigned g_bar_count = 0;

__device__ __forceinline__ void grid_sync(int nblocks) {
    __syncthreads();
    if (threadIdx.x == 0) {
        volatile unsigned* vgen = &g_bar_gen;
        __threadfence();                       // make this block's writes visible
        unsigned my = *vgen;                   // read BEFORE arriving
        unsigned t  = atomicAdd(&g_bar_count, 1u);
        if (t == (unsigned)nblocks - 1u) {
            g_bar_count = 0;
            __threadfence();
            *vgen = my + 1u;                   // release
        } else {
            while (*vgen == my) { __nanosleep(40); }
        }
        __threadfence();
    }
    __syncthreads();
}

// ---------------------------------------------------------------------------
// Fused persistent kernel. blockDim = 256. Requires D%4==0, D4<=256.
// ---------------------------------------------------------------------------
__global__ void __launch_bounds__(256)
pin_fused_kernel(const float* __restrict__ x,
                 const int*   __restrict__ seqlen,
                 const float* __restrict__ w,
                 const float* __restrict__ bias,
                 float*       __restrict__ out,
                 int B, int D4, int nblocks) {
    const int tid  = threadIdx.x;
    const int lane = tid % D4;
    const int grp  = tid / D4;
    const int ngrp = blockDim.x / D4;
    const int D    = D4 * 4;
    const int BD   = B * D;

    // Zero accumulators (must happen every graph replay).
    for (int i = blockIdx.x * blockDim.x + tid; i < BD;
         i += nblocks * blockDim.x) {
        g_sum[i] = 0.0f;
        g_sq [i] = 0.0f;
    }
    grid_sync(nblocks);

    // Affine params are segment-invariant: load once.
    float4 wv = make_float4(1.f, 1.f, 1.f, 1.f);
    float4 bv = make_float4(0.f, 0.f, 0.f, 0.f);
    if (lane < D4) {
        wv = __ldg(((const float4*)w)    + lane);
        bv = __ldg(((const float4*)bias) + lane);
    }

    __shared__ float4 s_sum[256];
    __shared__ float4 s_sq [256];

    const float4* __restrict__ x4 = (const float4*)x;
    float4*       __restrict__ o4 = (float4*)out;
    const long long slot0  = (long long)blockIdx.x * ngrp + grp;
    const long long stride = (long long)nblocks * ngrp;

    for (int b = 0; b < B; b++) {
        const long long s = seqlen[b];
        const long long e = seqlen[b + 1];

        // ---- Phase 1: reduce segment b ----
        float4 sum = make_float4(0.f, 0.f, 0.f, 0.f);
        float4 sq  = make_float4(0.f, 0.f, 0.f, 0.f);
        if (grp < ngrp) {
            for (long long r = s + slot0; r < e; r += stride) {
                float4 v = x4[r * D4 + lane];   // default caching: keep in L2
                sum.x += v.x; sum.y += v.y; sum.z += v.z; sum.w += v.w;
                sq.x  += v.x * v.x; sq.y += v.y * v.y;
                sq.z  += v.z * v.z; sq.w += v.w * v.w;
            }
        }
        s_sum[tid] = sum;
        s_sq [tid] = sq;
        __syncthreads();
        if (grp == 0) {
            for (int g = 1; g < ngrp; g++) {
                float4 a = s_sum[g * D4 + lane];
                float4 c = s_sq [g * D4 + lane];
                sum.x += a.x; sum.y += a.y; sum.z += a.z; sum.w += a.w;
                sq.x  += c.x; sq.y  += c.y; sq.z  += c.z; sq.w  += c.w;
            }
            const int base = b * D + lane * 4;
            atomicAdd(&g_sum[base + 0], sum.x);
            atomicAdd(&g_sum[base + 1], sum.y);
            atomicAdd(&g_sum[base + 2], sum.z);
            atomicAdd(&g_sum[base + 3], sum.w);
            atomicAdd(&g_sq [base + 0], sq.x);
            atomicAdd(&g_sq [base + 1], sq.y);
            atomicAdd(&g_sq [base + 2], sq.z);
            atomicAdd(&g_sq [base + 3], sq.w);
        }
        __syncthreads();   // shared reused next iter
        grid_sync(nblocks);

        // ---- Phase 2: local finalize (read L2-hot accumulators) ----
        float cnt   = (float)(e - s);
        float denom = fmaxf(cnt, 1.0f);
        float inv_n = 1.0f / denom;
        float4 sm = __ldcg(((const float4*)g_sum) + b * D4 + lane);
        float4 s2 = __ldcg(((const float4*)g_sq ) + b * D4 + lane);
        float4 mean, var, scale, shift;
        mean.x = sm.x * inv_n; mean.y = sm.y * inv_n;
        mean.z = sm.z * inv_n; mean.w = sm.w * inv_n;
        var.x = fmaxf(s2.x * inv_n - mean.x * mean.x, 0.f);
        var.y = fmaxf(s2.y * inv_n - mean.y * mean.y, 0.f);
        var.z = fmaxf(s2.z * inv_n - mean.z * mean.z, 0.f);
        var.w = fmaxf(s2.w * inv_n - mean.w * mean.w, 0.f);
        scale.x = rsqrtf(var.x + PIN_EPS) * wv.x;
        scale.y = rsqrtf(var.y + PIN_EPS) * wv.y;
        scale.z = rsqrtf(var.z + PIN_EPS) * wv.z;
        scale.w = rsqrtf(var.w + PIN_EPS) * wv.w;
        shift.x = bv.x - mean.x * scale.x;
        shift.y = bv.y - mean.y * scale.y;
        shift.z = bv.z - mean.z * scale.z;
        shift.w = bv.w - mean.w * scale.w;

        // ---- Phase 3: normalize segment b (x reads should hit L2) ----
        if (grp < ngrp) {
            for (long long r = s + slot0; r < e; r += stride) {
                float4 v = __ldcs(x4 + r * D4 + lane);   // last use: evict-first
                float4 o;
                o.x = fmaf(v.x, scale.x, shift.x);
                o.y = fmaf(v.y, scale.y, shift.y);
                o.z = fmaf(v.z, scale.z, shift.z);
                o.w = fmaf(v.w, scale.w, shift.w);
                __stcs(o4 + r * D4 + lane, o);            // streaming store
            }
        }
        // No barrier here: reduce(b+1) reads independent data, and the next
        // grid_sync keeps everyone within one segment of each other.
    }
}

// ---------------------------------------------------------------------------
// Fallback path (proven R3 kernels) for shapes the fused kernel can't take.
// ---------------------------------------------------------------------------
__global__ void pin_zero_kernel(int n) {
    int i = blockIdx.x * blockDim.x + threadIdx.x;
    if (i < n) { g_sum[i] = 0.0f; g_sq[i] = 0.0f; }
}

__global__ void pin_reduce_scalar(const float* __restrict__ x,
                                  const int*   __restrict__ seqlen,
                                  int D) {
    const int b = blockIdx.y;
    const int s = seqlen[b];
    const int e = seqlen[b + 1];
    const int L = e - s;
    const int nb = gridDim.x;
    const int chunk = (L + nb - 1) / nb;
    long long r0 = (long long)s + (long long)blockIdx.x * chunk;
    long long r1 = (long long)s + (long long)min((long long)L,
                                                 (long long)(blockIdx.x + 1) * (long long)chunk);
    for (int d = threadIdx.x; d < D; d += blockDim.x) {
        float sum = 0.f, sq = 0.f;
        for (long long r = r0; r < r1; r++) {
            float v = x[r * D + d];
            sum += v; sq += v * v;
        }
        atomicAdd(&g_sum[b * D + d], sum);
        atomicAdd(&g_sq [b * D + d], sq);
    }
}

__global__ void pin_finalize_kernel(const int*   __restrict__ seqlen,
                                    const float* __restrict__ w,
                                    const float* __restrict__ bias,
                                    int B, int D) {
    int i = blockIdx.x * blockDim.x + threadIdx.x;
    if (i >= B * D) return;
    int b = i / D;
    int d = i - b * D;
    float cnt   = (float)(seqlen[b + 1] - seqlen[b]);
    float denom = fmaxf(cnt, 1.0f);
    float mean  = g_sum[i] / denom;
    float var   = fmaxf(g_sq[i] / denom - mean * mean, 0.0f);
    float sc = rsqrtf(var + PIN_EPS) * w[d];
    g_scale[i] = sc;
    g_shift[i] = bias[d] - mean * sc;
}

__global__ void pin_norm_scalar(const float* __restrict__ x,
                                const int*   __restrict__ seqlen,
                                float*       __restrict__ out,
                                int D) {
    const int b = blockIdx.y;
    const int s = seqlen[b];
    const int e = seqlen[b + 1];
    const int L = e - s;
    const int nb = gridDim.x;
    const int chunk = (L + nb - 1) / nb;
    long long r0 = (long long)s + (long long)blockIdx.x * chunk;
    long long r1 = (long long)s + (long long)min((long long)L,
                                                 (long long)(blockIdx.x + 1) * (long long)chunk);
    for (long long r = r0; r < r1; r++) {
        for (int d = threadIdx.x; d < D; d += blockDim.x) {
            float v = x[r * D + d];
            out[r * D + d] = fmaf(v, g_scale[b * D + d], g_shift[b * D + d]);
        }
    }
}

extern "C" void kernel_launch(void* const* d_in, const int* in_sizes, int n_in,
                              void* d_out, int out_size) {
    const float* x      = (const float*)d_in[0];
    const int*   seqlen = (const int*)  d_in[1];
    const float* weight = (const float*)d_in[2];
    const float* bias   = (const float*)d_in[3];
    float*       out    = (float*)d_out;

    const int D  = in_sizes[2];          // weight is [1, D]
    const int B  = in_sizes[1] - 1;      // seqlen is [B+1]
    const long long N = (long long)in_sizes[0] / (D > 0 ? D : 1);
    const int BD = B * D;

    const int D4 = D / 4;
    const bool vec_ok = (D > 0) && (D % 4 == 0) && (D4 >= 1) && (D4 <= 256) &&
                        (BD <= PIN_MAXBD);

    int nblocks = 0;
    if (vec_ok) {
        int dev = 0;
        cudaGetDevice(&dev);
        int sms = 0;
        cudaDeviceGetAttribute(&sms, cudaDevAttrMultiProcessorCount, dev);
        int per_sm = 0;
        cudaOccupancyMaxActiveBlocksPerMultiprocessor(&per_sm, pin_fused_kernel,
                                                      256, 0);
        if (sms > 0 && per_sm > 0) {
            nblocks = sms * per_sm;           // guaranteed co-resident
            if (nblocks > 4096) nblocks = 4096;
        }
    }

    if (nblocks >= 2) {
        pin_fused_kernel<<<nblocks, 256>>>(x, seqlen, weight, bias, out,
                                           B, D4, nblocks);
        return;
    }

    // ---- Fallback: 4-kernel scalar pipeline (any shape) ----
    {
        int threads = 256;
        int blocks = (BD + threads - 1) / threads;
        if (blocks < 1) blocks = 1;
        pin_zero_kernel<<<blocks, threads>>>(BD);
    }
    int chunks = (int)((4096 + B - 1) / (B > 0 ? B : 1));
    long long avg_rows = (N + B - 1) / (B > 0 ? B : 1);
    if ((long long)chunks > avg_rows && avg_rows > 0) chunks = (int)avg_rows;
    if (chunks < 1) chunks = 1;
    dim3 grid(chunks, B > 0 ? B : 1);
    pin_reduce_scalar<<<grid, 256>>>(x, seqlen, D);
    {
        int threads = 256;
        int blocks = (BD + threads - 1) / threads;
        if (blocks < 1) blocks = 1;
        pin_finalize_kernel<<<blocks, threads>>>(seqlen, weight, bias, B, D);
    }
    pin_norm_scalar<<<grid, 256>>>(x, seqlen, out, D);
}